// round 1
// baseline (speedup 1.0000x reference)
#include <cuda_runtime.h>
#include <cuda_bf16.h>
#include <cstddef>

// Problem constants
// B=8, N=4096, C=512, NH=8, HD=64, R=8, h=w=64, M=64 (8x8 reduced map)

// Scratch (static __device__ allocations; no cudaMalloc allowed)
__device__ float g_q[(size_t)8 * 8 * 4096 * 64];   // [B][NH][N][HD]  64 MB
__device__ float g_kv[2 * 8 * 8 * 64 * 64];        // [2][B][NH][M][HD] 2 MB
__device__ float g_fmap[512 * 512];                // [B*M][C] post-LN
__device__ float g_scratch[16 * 512 * 512];        // conv split-K partials 16 MB
__device__ float g_attn[(size_t)8 * 4096 * 512];   // [B][N][C] attn output 64 MB

// ---------------------------------------------------------------------------
// 16-step inner MMA for 64x64 tile, 4x4 per thread (256 threads, 16x16)
// ---------------------------------------------------------------------------
__device__ __forceinline__ void mma16(const float As[16][65], const float Bs[16][64],
                                      int tx, int ty, float acc[4][4]) {
#pragma unroll
    for (int kk = 0; kk < 16; ++kk) {
        float4 bv = *reinterpret_cast<const float4*>(&Bs[kk][tx * 4]);
        float a0 = As[kk][ty * 4 + 0];
        float a1 = As[kk][ty * 4 + 1];
        float a2 = As[kk][ty * 4 + 2];
        float a3 = As[kk][ty * 4 + 3];
        acc[0][0] += a0 * bv.x; acc[0][1] += a0 * bv.y; acc[0][2] += a0 * bv.z; acc[0][3] += a0 * bv.w;
        acc[1][0] += a1 * bv.x; acc[1][1] += a1 * bv.y; acc[1][2] += a1 * bv.z; acc[1][3] += a1 * bv.w;
        acc[2][0] += a2 * bv.x; acc[2][1] += a2 * bv.y; acc[2][2] += a2 * bv.z; acc[2][3] += a2 * bv.w;
        acc[3][0] += a3 * bv.x; acc[3][1] += a3 * bv.y; acc[3][2] += a3 * bv.z; acc[3][3] += a3 * bv.w;
    }
}

// Generic mainloop for K=512, A row-major with stride 512, B row-major stride NCOLS
template <int NCOLS>
__device__ __forceinline__ void gemm_k512(const float* __restrict__ A,
                                          const float* __restrict__ Bm,
                                          int row0, int col0, float acc[4][4]) {
    __shared__ float As[16][65];
    __shared__ float Bs[16][64];
    const int tid = threadIdx.x;
    const int tx = tid & 15, ty = tid >> 4;
    const int lm = tid >> 2, lk = (tid & 3) * 4;   // A load: row lm, k offset lk (float4)
    const int bk = tid >> 4, bn = (tid & 15) * 4;  // B load: k row bk, col bn (float4)
    const float* aptr = A + (size_t)(row0 + lm) * 512 + lk;
    const float* bptr = Bm + (size_t)bk * NCOLS + col0 + bn;
    for (int k0 = 0; k0 < 512; k0 += 16) {
        float4 a4 = *reinterpret_cast<const float4*>(aptr + k0);
        As[lk + 0][lm] = a4.x; As[lk + 1][lm] = a4.y;
        As[lk + 2][lm] = a4.z; As[lk + 3][lm] = a4.w;
        float4 b4 = *reinterpret_cast<const float4*>(bptr + (size_t)k0 * NCOLS);
        *reinterpret_cast<float4*>(&Bs[bk][bn]) = b4;
        __syncthreads();
        mma16(As, Bs, tx, ty, acc);
        __syncthreads();
    }
}

// ---------------------------------------------------------------------------
// Conv as patch-GEMM with split-K: grid (8 ntiles, 8 mtiles, 16 ksplit)
// A[row, k]: row = b*64 + i*8 + j ; k = (r*8+s)*512 + ci
//   -> x[((b*4096 + (8i+r)*64 + 8j + s) * 512 + ci)]
// B[k, col] = conv_w[k*512 + col]   (HWIO flattened)
// ---------------------------------------------------------------------------
__global__ __launch_bounds__(256) void conv_gemm_kernel(const float* __restrict__ x,
                                                        const float* __restrict__ w) {
    __shared__ float As[16][65];
    __shared__ float Bs[16][64];
    const int tid = threadIdx.x;
    const int tx = tid & 15, ty = tid >> 4;
    const int lm = tid >> 2, lk = (tid & 3) * 4;
    const int bk = tid >> 4, bn = (tid & 15) * 4;
    const int row0 = blockIdx.y * 64, col0 = blockIdx.x * 64;
    const int kz = blockIdx.z;  // 0..15, each handles K-chunk of 2048
    const int arow = row0 + lm;
    const int ab = arow >> 6, ai = (arow >> 3) & 7, aj = arow & 7;
    float acc[4][4] = {};
    for (int k0 = 0; k0 < 2048; k0 += 16) {
        const int k = (kz << 11) + k0 + lk;
        const int ci = k & 511;
        const int rs = k >> 9;
        const int r = rs >> 3, s = rs & 7;
        const size_t apos =
            ((size_t)(ab * 4096 + (ai * 8 + r) * 64 + aj * 8 + s) << 9) + ci;
        float4 a4 = *reinterpret_cast<const float4*>(x + apos);
        As[lk + 0][lm] = a4.x; As[lk + 1][lm] = a4.y;
        As[lk + 2][lm] = a4.z; As[lk + 3][lm] = a4.w;
        const int kb = (kz << 11) + k0 + bk;
        float4 b4 = *reinterpret_cast<const float4*>(w + ((size_t)kb << 9) + col0 + bn);
        *reinterpret_cast<float4*>(&Bs[bk][bn]) = b4;
        __syncthreads();
        mma16(As, Bs, tx, ty, acc);
        __syncthreads();
    }
#pragma unroll
    for (int ii = 0; ii < 4; ++ii) {
        const int row = row0 + ty * 4 + ii;
#pragma unroll
        for (int jj = 0; jj < 4; ++jj) {
            const int col = col0 + tx * 4 + jj;
            g_scratch[(((size_t)kz * 512 + row) << 9) + col] = acc[ii][jj];
        }
    }
}

// ---------------------------------------------------------------------------
// Split-K reduce + LayerNorm fused. One block per row (512 rows), 256 threads.
// ---------------------------------------------------------------------------
__global__ __launch_bounds__(256) void ln_kernel(const float* __restrict__ gamma,
                                                 const float* __restrict__ beta) {
    const int row = blockIdx.x;
    const int tid = threadIdx.x;
    const int c0 = tid, c1 = tid + 256;
    float v0 = 0.f, v1 = 0.f;
#pragma unroll
    for (int kz = 0; kz < 16; ++kz) {
        const float* p = &g_scratch[((size_t)kz * 512 + row) << 9];
        v0 += p[c0];
        v1 += p[c1];
    }
    __shared__ float rs[256];
    __shared__ float rs2[256];
    rs[tid] = v0 + v1;
    rs2[tid] = v0 * v0 + v1 * v1;
    __syncthreads();
    for (int off = 128; off > 0; off >>= 1) {
        if (tid < off) {
            rs[tid] += rs[tid + off];
            rs2[tid] += rs2[tid + off];
        }
        __syncthreads();
    }
    const float mean = rs[0] * (1.f / 512.f);
    const float var = rs2[0] * (1.f / 512.f) - mean * mean;
    const float rstd = rsqrtf(var + 1e-3f);
    g_fmap[((size_t)row << 9) + c0] = (v0 - mean) * rstd * gamma[c0] + beta[c0];
    g_fmap[((size_t)row << 9) + c1] = (v1 - mean) * rstd * gamma[c1] + beta[c1];
}

// ---------------------------------------------------------------------------
// Q projection: [32768, 512] x [512, 512], scatter to [B][NH][N][HD]
// reshape 'b n (hd nh)': nh = col & 7, hd = col >> 3
// ---------------------------------------------------------------------------
__global__ __launch_bounds__(256) void gemm_q_kernel(const float* __restrict__ x,
                                                     const float* __restrict__ Wq) {
    const int row0 = blockIdx.y * 64, col0 = blockIdx.x * 64;
    float acc[4][4] = {};
    gemm_k512<512>(x, Wq, row0, col0, acc);
    const int tx = threadIdx.x & 15, ty = threadIdx.x >> 4;
#pragma unroll
    for (int ii = 0; ii < 4; ++ii) {
        const int row = row0 + ty * 4 + ii;
        const int b = row >> 12, n = row & 4095;
#pragma unroll
        for (int jj = 0; jj < 4; ++jj) {
            const int col = col0 + tx * 4 + jj;
            const int nh = col & 7, hd = col >> 3;
            g_q[(((size_t)b * 8 + nh) * 4096 + n) * 64 + hd] = acc[ii][jj];
        }
    }
}

// ---------------------------------------------------------------------------
// KV projection: [512, 512] x [512, 1024], scatter to [2][B][NH][M][HD]
// reshape 'b m (f nh hd)': f = col >> 9, nh = (col >> 6) & 7, hd = col & 63
// ---------------------------------------------------------------------------
__global__ __launch_bounds__(256) void gemm_kv_kernel(const float* __restrict__ Wkv) {
    const int row0 = blockIdx.y * 64, col0 = blockIdx.x * 64;
    float acc[4][4] = {};
    gemm_k512<1024>(g_fmap, Wkv, row0, col0, acc);
    const int tx = threadIdx.x & 15, ty = threadIdx.x >> 4;
#pragma unroll
    for (int ii = 0; ii < 4; ++ii) {
        const int row = row0 + ty * 4 + ii;
        const int b = row >> 6, m = row & 63;
#pragma unroll
        for (int jj = 0; jj < 4; ++jj) {
            const int col = col0 + tx * 4 + jj;
            const int f = col >> 9;
            const int nh = (col >> 6) & 7, hd = col & 63;
            g_kv[(size_t)f * 262144 + (((size_t)b * 8 + nh) * 64 + m) * 64 + hd] =
                acc[ii][jj];
        }
    }
}

// ---------------------------------------------------------------------------
// Attention: per (b,nh) K/V are [64, 64] -> fit in smem. One thread per query
// row, online softmax, q row + output accumulator in registers.
// Output layout: [B][N][C] with c = nh*64 + hd (post-transpose reshape).
// ---------------------------------------------------------------------------
__global__ __launch_bounds__(128) void attn_kernel() {
    __shared__ float ks[64][64];
    __shared__ float vs[64][64];
    const int bh = blockIdx.x;  // b*8 + nh
    const int b = bh >> 3, nh = bh & 7;
    const int tid = threadIdx.x;
    const float* kb = g_kv + (size_t)bh * 4096;
    const float* vb = g_kv + 262144 + (size_t)bh * 4096;
#pragma unroll
    for (int idx = tid * 4; idx < 4096; idx += 128 * 4) {
        *reinterpret_cast<float4*>(&ks[0][0] + idx) =
            *reinterpret_cast<const float4*>(kb + idx);
        *reinterpret_cast<float4*>(&vs[0][0] + idx) =
            *reinterpret_cast<const float4*>(vb + idx);
    }
    __syncthreads();

    const int n = blockIdx.y * 128 + tid;
    const float* qrow = g_q + ((size_t)bh * 4096 + n) * 64;
    float qr[64];
#pragma unroll
    for (int d = 0; d < 64; d += 4) {
        float4 t = *reinterpret_cast<const float4*>(qrow + d);
        qr[d] = t.x; qr[d + 1] = t.y; qr[d + 2] = t.z; qr[d + 3] = t.w;
    }
    float o[64];
#pragma unroll
    for (int d = 0; d < 64; ++d) o[d] = 0.f;
    float mx = -1e30f, sum = 0.f;
    const float scale = 0.125f;  // 1/sqrt(64)
    for (int m = 0; m < 64; ++m) {
        float acc = 0.f;
#pragma unroll
        for (int d = 0; d < 64; ++d) acc += qr[d] * ks[m][d];
        acc *= scale;
        const float nmx = fmaxf(mx, acc);
        const float corr = __expf(mx - nmx);
        const float p = __expf(acc - nmx);
        sum = sum * corr + p;
#pragma unroll
        for (int d = 0; d < 64; ++d) o[d] = o[d] * corr + p * vs[m][d];
        mx = nmx;
    }
    const float inv = 1.f / sum;
    float* orow = g_attn + ((size_t)(b * 4096 + n)) * 512 + nh * 64;
#pragma unroll
    for (int d = 0; d < 64; ++d) orow[d] = o[d] * inv;
}

// ---------------------------------------------------------------------------
// Output projection: [32768, 512] x [512, 512] + bias -> d_out [B][N][C]
// ---------------------------------------------------------------------------
__global__ __launch_bounds__(256) void gemm_proj_kernel(const float* __restrict__ Wp,
                                                        const float* __restrict__ bp,
                                                        float* __restrict__ out) {
    const int row0 = blockIdx.y * 64, col0 = blockIdx.x * 64;
    float acc[4][4] = {};
    gemm_k512<512>(g_attn, Wp, row0, col0, acc);
    const int tx = threadIdx.x & 15, ty = threadIdx.x >> 4;
#pragma unroll
    for (int ii = 0; ii < 4; ++ii) {
        const int row = row0 + ty * 4 + ii;
#pragma unroll
        for (int jj = 0; jj < 4; ++jj) {
            const int col = col0 + tx * 4 + jj;
            out[((size_t)row << 9) + col] = acc[ii][jj] + bp[col];
        }
    }
}

// ---------------------------------------------------------------------------
extern "C" void kernel_launch(void* const* d_in, const int* in_sizes, int n_in,
                              void* d_out, int out_size) {
    const float* x      = (const float*)d_in[0];
    const float* Wq     = (const float*)d_in[1];
    const float* Wkv    = (const float*)d_in[2];
    const float* conv_w = (const float*)d_in[3];
    const float* gamma  = (const float*)d_in[4];
    const float* beta   = (const float*)d_in[5];
    const float* Wp     = (const float*)d_in[6];
    const float* bp     = (const float*)d_in[7];
    float* out = (float*)d_out;

    // KV path: conv(split-K) -> reduce+LN -> KV GEMM
    conv_gemm_kernel<<<dim3(8, 8, 16), 256>>>(x, conv_w);
    ln_kernel<<<512, 256>>>(gamma, beta);
    gemm_kv_kernel<<<dim3(16, 8), 256>>>(Wkv);

    // Q path (independent of KV path ordering; same stream serializes anyway)
    gemm_q_kernel<<<dim3(8, 512), 256>>>(x, Wq);

    // Attention over 64 KV tokens per (b, nh)
    attn_kernel<<<dim3(64, 32), 128>>>();

    // Output projection
    gemm_proj_kernel<<<dim3(8, 512), 256>>>(Wp, bp, out);
}

// round 2
// speedup vs baseline: 1.1715x; 1.1715x over previous
#include <cuda_runtime.h>
#include <cuda_bf16.h>
#include <cstddef>

// B=8, N=4096, C=512, NH=8, HD=64, R=8, h=w=64, M=64

__device__ float g_q[(size_t)8 * 8 * 4096 * 64];   // [B][NH][N][HD]  64 MB
__device__ float g_kv[2 * 8 * 8 * 64 * 64];        // [2][B][NH][M][HD]
__device__ float g_fmap[512 * 512];                // [B*M][C] post-LN
__device__ float g_scratch[(size_t)32 * 512 * 512];// conv split-K partials 32 MB
__device__ float g_attn[(size_t)8 * 4096 * 512];   // [B][N][C] attn output

// ===========================================================================
// 128x128 tile GEMM machinery: 256 threads, 8x8 per thread, K-step 8,
// double-buffered smem.
// ===========================================================================
#define AS_STRIDE 132

__device__ __forceinline__ void compute8(const float (*As)[AS_STRIDE],
                                         const float (*Bs)[128],
                                         int tx, int ty, float (&acc)[8][8]) {
#pragma unroll
    for (int k = 0; k < 8; ++k) {
        float ar[8], br[8];
        *reinterpret_cast<float4*>(ar)     = *reinterpret_cast<const float4*>(&As[k][ty * 8]);
        *reinterpret_cast<float4*>(ar + 4) = *reinterpret_cast<const float4*>(&As[k][ty * 8 + 4]);
        *reinterpret_cast<float4*>(br)     = *reinterpret_cast<const float4*>(&Bs[k][tx * 8]);
        *reinterpret_cast<float4*>(br + 4) = *reinterpret_cast<const float4*>(&Bs[k][tx * 8 + 4]);
#pragma unroll
        for (int i = 0; i < 8; ++i)
#pragma unroll
            for (int j = 0; j < 8; ++j)
                acc[i][j] += ar[i] * br[j];
    }
}

// Mainloop for A row-major stride 512 (K=512), B row-major stride NCOLS.
template <int NCOLS>
__device__ __forceinline__ void gemm128_k512(const float* __restrict__ A,
                                             const float* __restrict__ Bm,
                                             int row0, int col0,
                                             float (&acc)[8][8]) {
    __shared__ float As[2][8][AS_STRIDE];
    __shared__ float Bs[2][8][128];
    const int tid = threadIdx.x;
    const int arow = tid >> 1, acol = (tid & 1) * 4;
    const int brow = tid >> 5, bcol = (tid & 31) * 4;
    const int tx = tid & 15, ty = tid >> 4;
    const float* aptr = A + (size_t)(row0 + arow) * 512 + acol;
    const float* bptr = Bm + (size_t)brow * NCOLS + col0 + bcol;

    float4 a4 = *reinterpret_cast<const float4*>(aptr);
    float4 b4 = *reinterpret_cast<const float4*>(bptr);
    As[0][acol + 0][arow] = a4.x; As[0][acol + 1][arow] = a4.y;
    As[0][acol + 2][arow] = a4.z; As[0][acol + 3][arow] = a4.w;
    *reinterpret_cast<float4*>(&Bs[0][brow][bcol]) = b4;
    __syncthreads();

#pragma unroll 1
    for (int kb = 0; kb < 64; ++kb) {
        const int cur = kb & 1;
        if (kb < 63) {
            a4 = *reinterpret_cast<const float4*>(aptr + (kb + 1) * 8);
            b4 = *reinterpret_cast<const float4*>(bptr + (size_t)(kb + 1) * 8 * NCOLS);
        }
        compute8(As[cur], Bs[cur], tx, ty, acc);
        if (kb < 63) {
            const int nxt = cur ^ 1;
            As[nxt][acol + 0][arow] = a4.x; As[nxt][acol + 1][arow] = a4.y;
            As[nxt][acol + 2][arow] = a4.z; As[nxt][acol + 3][arow] = a4.w;
            *reinterpret_cast<float4*>(&Bs[nxt][brow][bcol]) = b4;
            __syncthreads();
        }
    }
}

// ===========================================================================
// Conv as patch-GEMM, 128x128 tile, split-K=32 (K-chunk 1024 of 32768).
// A[row,k]: row=b*64+i*8+j, k=(r*8+s)*512+ci -> x[(b*4096+(8i+r)*64+8j+s)*512+ci]
// ===========================================================================
__global__ __launch_bounds__(256) void conv_gemm_kernel(const float* __restrict__ x,
                                                        const float* __restrict__ w) {
    __shared__ float As[2][8][AS_STRIDE];
    __shared__ float Bs[2][8][128];
    const int tid = threadIdx.x;
    const int arow = tid >> 1, acol = (tid & 1) * 4;
    const int brow = tid >> 5, bcol = (tid & 31) * 4;
    const int tx = tid & 15, ty = tid >> 4;
    const int row0 = blockIdx.y * 128, col0 = blockIdx.x * 128;
    const int kzbase = blockIdx.z << 10;   // K-chunk of 1024

    const int row = row0 + arow;
    const int b = row >> 6, pi = (row >> 3) & 7, pj = row & 7;
    const int pixbase = b * 4096 + pi * 8 * 64 + pj * 8;  // + r*64 + s

    const float* bptr = w + ((size_t)(kzbase + brow) << 9) + col0 + bcol;

    float acc[8][8] = {};

    // initial fetch kb=0
    {
        const int k = kzbase + acol;
        const int ci = k & 511, rs = k >> 9, r = rs >> 3, s = rs & 7;
        float4 a4 = *reinterpret_cast<const float4*>(
            x + ((size_t)(pixbase + r * 64 + s) << 9) + ci);
        float4 b4 = *reinterpret_cast<const float4*>(bptr);
        As[0][acol + 0][arow] = a4.x; As[0][acol + 1][arow] = a4.y;
        As[0][acol + 2][arow] = a4.z; As[0][acol + 3][arow] = a4.w;
        *reinterpret_cast<float4*>(&Bs[0][brow][bcol]) = b4;
    }
    __syncthreads();

#pragma unroll 1
    for (int kb = 0; kb < 128; ++kb) {
        const int cur = kb & 1;
        float4 a4, b4;
        if (kb < 127) {
            const int k = kzbase + (kb + 1) * 8 + acol;
            const int ci = k & 511, rs = k >> 9, r = rs >> 3, s = rs & 7;
            a4 = *reinterpret_cast<const float4*>(
                x + ((size_t)(pixbase + r * 64 + s) << 9) + ci);
            b4 = *reinterpret_cast<const float4*>(bptr + (size_t)(kb + 1) * 8 * 512);
        }
        compute8(As[cur], Bs[cur], tx, ty, acc);
        if (kb < 127) {
            const int nxt = cur ^ 1;
            As[nxt][acol + 0][arow] = a4.x; As[nxt][acol + 1][arow] = a4.y;
            As[nxt][acol + 2][arow] = a4.z; As[nxt][acol + 3][arow] = a4.w;
            *reinterpret_cast<float4*>(&Bs[nxt][brow][bcol]) = b4;
            __syncthreads();
        }
    }

    float* dst = g_scratch + ((size_t)blockIdx.z << 18);
#pragma unroll
    for (int i = 0; i < 8; ++i) {
        const int r = row0 + ty * 8 + i;
        float* p = dst + ((size_t)r << 9) + col0 + tx * 8;
        *reinterpret_cast<float4*>(p)     = *reinterpret_cast<float4*>(&acc[i][0]);
        *reinterpret_cast<float4*>(p + 4) = *reinterpret_cast<float4*>(&acc[i][4]);
    }
}

// ===========================================================================
// Split-K reduce + LayerNorm. One block per row (512 rows), 256 threads.
// ===========================================================================
__global__ __launch_bounds__(256) void ln_kernel(const float* __restrict__ gamma,
                                                 const float* __restrict__ beta) {
    const int row = blockIdx.x;
    const int tid = threadIdx.x;
    const int c0 = tid, c1 = tid + 256;
    float v0 = 0.f, v1 = 0.f;
#pragma unroll
    for (int kz = 0; kz < 32; ++kz) {
        const float* p = &g_scratch[((size_t)kz << 18) + ((size_t)row << 9)];
        v0 += p[c0];
        v1 += p[c1];
    }
    __shared__ float rs[256];
    __shared__ float rs2[256];
    rs[tid] = v0 + v1;
    rs2[tid] = v0 * v0 + v1 * v1;
    __syncthreads();
    for (int off = 128; off > 0; off >>= 1) {
        if (tid < off) {
            rs[tid] += rs[tid + off];
            rs2[tid] += rs2[tid + off];
        }
        __syncthreads();
    }
    const float mean = rs[0] * (1.f / 512.f);
    const float var = rs2[0] * (1.f / 512.f) - mean * mean;
    const float rstd = rsqrtf(var + 1e-3f);
    g_fmap[((size_t)row << 9) + c0] = (v0 - mean) * rstd * gamma[c0] + beta[c0];
    g_fmap[((size_t)row << 9) + c1] = (v1 - mean) * rstd * gamma[c1] + beta[c1];
}

// ===========================================================================
// Q projection: [32768,512]x[512,512], scatter to [B][NH][N][HD]
// col -> nh = col & 7, hd = col >> 3
// ===========================================================================
__global__ __launch_bounds__(256) void gemm_q_kernel(const float* __restrict__ x,
                                                     const float* __restrict__ Wq) {
    const int row0 = blockIdx.y * 128, col0 = blockIdx.x * 128;
    float acc[8][8] = {};
    gemm128_k512<512>(x, Wq, row0, col0, acc);
    const int tx = threadIdx.x & 15, ty = threadIdx.x >> 4;
#pragma unroll
    for (int i = 0; i < 8; ++i) {
        const int row = row0 + ty * 8 + i;
        const int b = row >> 12, n = row & 4095;
#pragma unroll
        for (int j = 0; j < 8; ++j) {
            const int col = col0 + tx * 8 + j;
            const int nh = col & 7, hd = col >> 3;
            g_q[(((size_t)b * 8 + nh) * 4096 + n) * 64 + hd] = acc[i][j];
        }
    }
}

// ===========================================================================
// Output projection + bias: A = g_attn, out coalesced.
// ===========================================================================
__global__ __launch_bounds__(256) void gemm_proj_kernel(const float* __restrict__ Wp,
                                                        const float* __restrict__ bp,
                                                        float* __restrict__ out) {
    const int row0 = blockIdx.y * 128, col0 = blockIdx.x * 128;
    float acc[8][8] = {};
    gemm128_k512<512>(g_attn, Wp, row0, col0, acc);
    const int tx = threadIdx.x & 15, ty = threadIdx.x >> 4;
    const int colb = col0 + tx * 8;
    float bias[8];
    *reinterpret_cast<float4*>(bias)     = *reinterpret_cast<const float4*>(bp + colb);
    *reinterpret_cast<float4*>(bias + 4) = *reinterpret_cast<const float4*>(bp + colb + 4);
#pragma unroll
    for (int i = 0; i < 8; ++i) {
        const int row = row0 + ty * 8 + i;
        float v[8];
#pragma unroll
        for (int j = 0; j < 8; ++j) v[j] = acc[i][j] + bias[j];
        float* p = out + ((size_t)row << 9) + colb;
        *reinterpret_cast<float4*>(p)     = *reinterpret_cast<float4*>(v);
        *reinterpret_cast<float4*>(p + 4) = *reinterpret_cast<float4*>(v + 4);
    }
}

// ===========================================================================
// KV projection (small: 512x1024x512) — 64x64 tile, 4x4/thread (round-0 code)
// ===========================================================================
__device__ __forceinline__ void mma16(const float As[16][65], const float Bs[16][64],
                                      int tx, int ty, float acc[4][4]) {
#pragma unroll
    for (int kk = 0; kk < 16; ++kk) {
        float4 bv = *reinterpret_cast<const float4*>(&Bs[kk][tx * 4]);
        float a0 = As[kk][ty * 4 + 0];
        float a1 = As[kk][ty * 4 + 1];
        float a2 = As[kk][ty * 4 + 2];
        float a3 = As[kk][ty * 4 + 3];
        acc[0][0] += a0 * bv.x; acc[0][1] += a0 * bv.y; acc[0][2] += a0 * bv.z; acc[0][3] += a0 * bv.w;
        acc[1][0] += a1 * bv.x; acc[1][1] += a1 * bv.y; acc[1][2] += a1 * bv.z; acc[1][3] += a1 * bv.w;
        acc[2][0] += a2 * bv.x; acc[2][1] += a2 * bv.y; acc[2][2] += a2 * bv.z; acc[2][3] += a2 * bv.w;
        acc[3][0] += a3 * bv.x; acc[3][1] += a3 * bv.y; acc[3][2] += a3 * bv.z; acc[3][3] += a3 * bv.w;
    }
}

__global__ __launch_bounds__(256) void gemm_kv_kernel(const float* __restrict__ Wkv) {
    __shared__ float As[16][65];
    __shared__ float Bs[16][64];
    const int tid = threadIdx.x;
    const int tx = tid & 15, ty = tid >> 4;
    const int lm = tid >> 2, lk = (tid & 3) * 4;
    const int bk = tid >> 4, bn = (tid & 15) * 4;
    const int row0 = blockIdx.y * 64, col0 = blockIdx.x * 64;
    const float* aptr = g_fmap + (size_t)(row0 + lm) * 512 + lk;
    const float* bptr = Wkv + (size_t)bk * 1024 + col0 + bn;
    float acc[4][4] = {};
    for (int k0 = 0; k0 < 512; k0 += 16) {
        float4 a4 = *reinterpret_cast<const float4*>(aptr + k0);
        As[lk + 0][lm] = a4.x; As[lk + 1][lm] = a4.y;
        As[lk + 2][lm] = a4.z; As[lk + 3][lm] = a4.w;
        float4 b4 = *reinterpret_cast<const float4*>(bptr + (size_t)k0 * 1024);
        *reinterpret_cast<float4*>(&Bs[bk][bn]) = b4;
        __syncthreads();
        mma16(As, Bs, tx, ty, acc);
        __syncthreads();
    }
#pragma unroll
    for (int ii = 0; ii < 4; ++ii) {
        const int row = row0 + ty * 4 + ii;
        const int b = row >> 6, m = row & 63;
#pragma unroll
        for (int jj = 0; jj < 4; ++jj) {
            const int col = col0 + tx * 4 + jj;
            const int f = col >> 9;
            const int nh = (col >> 6) & 7, hd = col & 63;
            g_kv[(size_t)f * 262144 + (((size_t)b * 8 + nh) * 64 + m) * 64 + hd] =
                acc[ii][jj];
        }
    }
}

// ===========================================================================
// Attention: per (b,nh) K/V are [64,64] in smem. 1 thread per query row.
// ===========================================================================
__global__ __launch_bounds__(128) void attn_kernel() {
    __shared__ float ks[64][64];
    __shared__ float vs[64][64];
    const int bh = blockIdx.x;
    const int b = bh >> 3, nh = bh & 7;
    const int tid = threadIdx.x;
    const float* kb = g_kv + (size_t)bh * 4096;
    const float* vb = g_kv + 262144 + (size_t)bh * 4096;
#pragma unroll
    for (int idx = tid * 4; idx < 4096; idx += 128 * 4) {
        *reinterpret_cast<float4*>(&ks[0][0] + idx) =
            *reinterpret_cast<const float4*>(kb + idx);
        *reinterpret_cast<float4*>(&vs[0][0] + idx) =
            *reinterpret_cast<const float4*>(vb + idx);
    }
    __syncthreads();

    const int n = blockIdx.y * 128 + tid;
    const float* qrow = g_q + ((size_t)bh * 4096 + n) * 64;
    float qr[64];
#pragma unroll
    for (int d = 0; d < 64; d += 4) {
        float4 t = *reinterpret_cast<const float4*>(qrow + d);
        qr[d] = t.x; qr[d + 1] = t.y; qr[d + 2] = t.z; qr[d + 3] = t.w;
    }
    float o[64];
#pragma unroll
    for (int d = 0; d < 64; ++d) o[d] = 0.f;
    float mx = -1e30f, sum = 0.f;
    const float scale = 0.125f;
    for (int m = 0; m < 64; ++m) {
        float acc = 0.f;
#pragma unroll
        for (int d4 = 0; d4 < 16; ++d4) {
            float4 k4 = *reinterpret_cast<const float4*>(&ks[m][d4 * 4]);
            acc += qr[d4 * 4] * k4.x + qr[d4 * 4 + 1] * k4.y +
                   qr[d4 * 4 + 2] * k4.z + qr[d4 * 4 + 3] * k4.w;
        }
        acc *= scale;
        const float nmx = fmaxf(mx, acc);
        const float corr = __expf(mx - nmx);
        const float p = __expf(acc - nmx);
        sum = sum * corr + p;
#pragma unroll
        for (int d4 = 0; d4 < 16; ++d4) {
            float4 v4 = *reinterpret_cast<const float4*>(&vs[m][d4 * 4]);
            o[d4 * 4]     = o[d4 * 4]     * corr + p * v4.x;
            o[d4 * 4 + 1] = o[d4 * 4 + 1] * corr + p * v4.y;
            o[d4 * 4 + 2] = o[d4 * 4 + 2] * corr + p * v4.z;
            o[d4 * 4 + 3] = o[d4 * 4 + 3] * corr + p * v4.w;
        }
        mx = nmx;
    }
    const float inv = 1.f / sum;
    float* orow = g_attn + ((size_t)(b * 4096 + n)) * 512 + nh * 64;
#pragma unroll
    for (int d = 0; d < 64; d += 4) {
        float4 t;
        t.x = o[d] * inv; t.y = o[d + 1] * inv;
        t.z = o[d + 2] * inv; t.w = o[d + 3] * inv;
        *reinterpret_cast<float4*>(orow + d) = t;
    }
}

// ===========================================================================
extern "C" void kernel_launch(void* const* d_in, const int* in_sizes, int n_in,
                              void* d_out, int out_size) {
    const float* x      = (const float*)d_in[0];
    const float* Wq     = (const float*)d_in[1];
    const float* Wkv    = (const float*)d_in[2];
    const float* conv_w = (const float*)d_in[3];
    const float* gamma  = (const float*)d_in[4];
    const float* beta   = (const float*)d_in[5];
    const float* Wp     = (const float*)d_in[6];
    const float* bp     = (const float*)d_in[7];
    float* out = (float*)d_out;

    conv_gemm_kernel<<<dim3(4, 4, 32), 256>>>(x, conv_w);
    ln_kernel<<<512, 256>>>(gamma, beta);
    gemm_kv_kernel<<<dim3(16, 8), 256>>>(Wkv);

    gemm_q_kernel<<<dim3(4, 256), 256>>>(x, Wq);

    attn_kernel<<<dim3(64, 32), 128>>>();

    gemm_proj_kernel<<<dim3(4, 256), 256>>>(Wp, bp, out);
}